// round 6
// baseline (speedup 1.0000x reference)
#include <cuda_runtime.h>
#include <cstdint>

#define BNUM 4
#define HS 64
#define WS 64
#define HU 512
#define WU 512
#define CORI 90
#define CMNT 180
#define COFF 8
#define KCAND 1024
#define NCELL (HS*WS)       // 4096
#define NPIX (HU*WU)        // 262144

// output layout: minut [4,1024,4] | keep [4,1024] | enh_vis | mask_up*255 | ori_field
#define MINUT_OFF 0
#define KEEP_OFF  16384
#define ENH_OFF   20480
#define MASK_OFF  1069056
#define ORI_OFF   2117632

__device__ float g_mask[BNUM*NCELL];
__device__ float g_tA[BNUM*NPIX];
__device__ float g_tB[BNUM*NPIX];
__device__ float g_maskup[BNUM*NPIX];
__device__ unsigned g_emin[BNUM];
__device__ unsigned g_emax[BNUM];

__device__ __forceinline__ unsigned f2ord(float f){
    unsigned u=__float_as_uint(f);
    return (u & 0x80000000u) ? ~u : (u | 0x80000000u);
}
__device__ __forceinline__ float ord2f(unsigned u){
    u = (u & 0x80000000u) ? (u & 0x7fffffffu) : ~u;
    return __uint_as_float(u);
}

// ---------- fused 5x5 opening on [B,64,64] + minmax init ----------
__global__ void __launch_bounds__(1024) opening_small(const float* __restrict__ seg){
    __shared__ float s0[NCELL];
    __shared__ float s1[NCELL];
    int b=blockIdx.x, tid=threadIdx.x;
    if(b==0 && tid<BNUM){ g_emin[tid]=0xFFFFFFFFu; g_emax[tid]=0u; }
    const float* sg=seg+(size_t)b*NCELL;
    for(int t=tid;t<NCELL;t+=1024) s0[t]=rintf(sg[t]);
    __syncthreads();
    for(int t=tid;t<NCELL;t+=1024){
        int r=t>>6, c=t&63;
        int y0=max(r-2,0), y1=min(r+2,HS-1), x0=max(c-2,0), x1=min(c+2,WS-1);
        float m=1e30f;
        for(int y=y0;y<=y1;y++)
            for(int x=x0;x<=x1;x++)
                m=fminf(m,s0[(y<<6)+x]);
        s1[t]=m;
    }
    __syncthreads();
    for(int t=tid;t<NCELL;t+=1024){
        int r=t>>6, c=t&63;
        int y0=max(r-2,0), y1=min(r+2,HS-1), x0=max(c-2,0), x1=min(c+2,WS-1);
        float m=-1e30f;
        for(int y=y0;y<=y1;y++)
            for(int x=x0;x<=x1;x++)
                m=fmaxf(m,s1[(y<<6)+x]);
        g_mask[(size_t)b*NCELL+t]=m;
    }
}

// ---------- 512x512 transpose, 32x32 smem tiles (proven shape) ----------
__global__ void __launch_bounds__(256) transpose512(const float* __restrict__ in,
                                                    float* __restrict__ out){
    __shared__ float t[32][33];
    int b=blockIdx.z;
    int x0=blockIdx.x*32, y0=blockIdx.y*32;
    const float* s=in +(size_t)b*NPIX;
    float*       d=out+(size_t)b*NPIX;
    int tx=threadIdx.x, ty=threadIdx.y;   // (32,8)
    #pragma unroll
    for(int k=0;k<32;k+=8)
        t[ty+k][tx]=s[(size_t)(y0+ty+k)*WU + x0+tx];
    __syncthreads();
    #pragma unroll
    for(int k=0;k<32;k+=8)
        d[(size_t)(x0+ty+k)*WU + y0+tx]=t[tx][ty+k];
}

// ---------- horizontal pool (win40 = op over [x-19,x+20]): doubling tree ----------
// one block per row; grid (512, BNUM). Proven 3.26us shape.
template<bool MN, bool RND, bool FUSED>
__global__ void __launch_bounds__(256) hpool(const float* __restrict__ in, float* __restrict__ outb,
                      const float* __restrict__ enh, float* __restrict__ outg){
    __shared__ float sA[552], sB[552], s8[552];
    __shared__ float rmn[8], rmx[8];
    int row = blockIdx.x, b = blockIdx.y, tid = threadIdx.x;
    const float* src = in + ((size_t)b*HU + row)*WU;
    const float NEU = MN?1e30f:-1e30f;
    #define OPX(a,c) (MN?fminf(a,c):fmaxf(a,c))
    for(int i=tid;i<551;i+=256){
        float v = (i>=19 && i<19+WU) ? src[i-19] : NEU;
        if(RND) v=rintf(v);
        sA[i]=v;
    }
    __syncthreads();
    for(int i=tid;i<550;i+=256) sB[i]=OPX(sA[i],sA[i+1]);
    __syncthreads();
    for(int i=tid;i<548;i+=256) sA[i]=OPX(sB[i],sB[i+2]);
    __syncthreads();
    for(int i=tid;i<544;i+=256) s8[i]=OPX(sA[i],sA[i+4]);
    __syncthreads();
    for(int i=tid;i<536;i+=256) sB[i]=OPX(s8[i],s8[i+8]);
    __syncthreads();
    for(int i=tid;i<520;i+=256) sA[i]=OPX(sB[i],sB[i+16]);
    __syncthreads();
    float* dst = outb + ((size_t)b*HU+row)*WU;
    if(!FUSED){
        for(int x=tid;x<WU;x+=256) dst[x]=OPX(sA[x], s8[x+32]);
    } else {
        const float* erow = enh + ((size_t)b*HU+row)*WU;
        float mn=1e30f, mx=-1e30f;
        for(int x=tid;x<WU;x+=256){
            float m=OPX(sA[x], s8[x+32]);
            dst[x]=m;
            outg[MASK_OFF + ((size_t)b*HU+row)*WU + x] = m*255.0f;
            float ev = erow[x]*m;
            mn=fminf(mn,ev); mx=fmaxf(mx,ev);
        }
        #pragma unroll
        for(int o=16;o;o>>=1){
            mn=fminf(mn,__shfl_xor_sync(0xFFFFFFFFu,mn,o));
            mx=fmaxf(mx,__shfl_xor_sync(0xFFFFFFFFu,mx,o));
        }
        int lane=tid&31, w=tid>>5;
        if(lane==0){ rmn[w]=mn; rmx[w]=mx; }
        __syncthreads();
        if(tid==0){
            for(int i=1;i<8;i++){ mn=fminf(mn,rmn[i]); mx=fmaxf(mx,rmx[i]); }
            atomicMin(&g_emin[b], f2ord(mn));
            atomicMax(&g_emax[b], f2ord(mx));
        }
    }
    #undef OPX
}

// ---------- detect: top-k + NMS, one block per batch ----------
__global__ void __launch_bounds__(1024) detect_nms(
    const float* __restrict__ mscore, const float* __restrict__ mori,
    const float* __restrict__ mxo,    const float* __restrict__ myo,
    float* __restrict__ out)
{
    int b=blockIdx.x, tid=threadIdx.x;
    __shared__ unsigned long long keys[4096];   // 32KB
    __shared__ int s_nv;
    float* sx=(float*)(keys+1024);
    float* sy=(float*)(keys+1536);
    float* sa=(float*)(keys+2048);
    unsigned char* skeep=(unsigned char*)(keys+2560);

    const float* sc=mscore+(size_t)b*NCELL;
    const float* mk=g_mask +(size_t)b*NCELL;

    bool anyv=false;
    for(int t=tid;t<NCELL;t+=1024){
        float v=sc[t]*mk[t];
        bool val = v>0.5f;
        anyv |= val;
        float mv = val ? v : -1.0f;
        keys[t] = ((unsigned long long)(~f2ord(mv))<<32) | (unsigned)t;
    }
    if(__syncthreads_count(anyv)==0){
        float* om=out + MINUT_OFF + (size_t)b*KCAND*4 + (size_t)tid*4;
        om[0]=0.0f; om[1]=0.0f; om[2]=0.0f; om[3]=0.0f;
        out[KEEP_OFF + (size_t)b*KCAND + tid]=0.0f;
        return;
    }
    for(int k=2;k<=4096;k<<=1){
        for(int j=k>>1;j>0;j>>=1){
            for(int i=tid;i<4096;i+=1024){
                int ixj=i^j;
                if(ixj>i){
                    unsigned long long a=keys[i], c=keys[ixj];
                    bool up=((i&k)==0);
                    if((a>c)==up){ keys[i]=c; keys[ixj]=a; }
                }
            }
            __syncthreads();
        }
    }
    unsigned long long key=keys[tid];
    int idx=(int)(key & 0xFFFFFFFFull);
    float mv = ord2f(~(unsigned)(key>>32));
    bool valid = mv>0.5f;
    float score = valid ? mv : 0.0f;
    float xc=0.0f, yc=0.0f, ang=0.0f;
    if(valid){
        int r=idx>>6, c=idx&63;
        const float* o=mori+(size_t)b*CMNT*NCELL+idx;
        int ai=0; float bv=o[0];
        for(int ch=1;ch<CMNT;ch++){ float v=o[(size_t)ch*NCELL]; if(v>bv){bv=v;ai=ch;} }
        const float* xo=mxo+(size_t)b*COFF*NCELL+idx;
        int xi=0; float bx=xo[0];
        for(int ch=1;ch<COFF;ch++){ float v=xo[(size_t)ch*NCELL]; if(v>bx){bx=v;xi=ch;} }
        const float* yo=myo+(size_t)b*COFF*NCELL+idx;
        int yi=0; float by=yo[0];
        for(int ch=1;ch<COFF;ch++){ float v=yo[(size_t)ch*NCELL]; if(v>by){by=v;yi=ch;} }
        ang=((float)ai*2.0f-89.0f)*0.017453292519943295f;
        xc=(float)c*8.0f+(float)xi;
        yc=(float)r*8.0f+(float)yi;
    }
    if(tid==0) s_nv=0;
    __syncthreads();
    sx[tid]=xc; sy[tid]=yc; sa[tid]=ang; skeep[tid]=valid?1:0;
    atomicMax(&s_nv, valid?(tid+1):0);
    __syncthreads();
    int nv=s_nv;
    for(int i=0;i<nv;i++){
        if(skeep[i] && tid>i && skeep[tid]){
            float dx=sx[tid]-sx[i], dy=sy[tid]-sy[i];
            float d=sqrtf(dx*dx+dy*dy);
            float da=fabsf(sa[tid]-sa[i]);
            da=fminf(da, 6.2831853071795864f-da);
            if(d<16.0f && da<0.52359877559829887f) skeep[tid]=0;
        }
        __syncthreads();
    }
    float kf = skeep[tid]?1.0f:0.0f;
    float* om=out + MINUT_OFF + (size_t)b*KCAND*4 + (size_t)tid*4;
    om[0]=kf*xc; om[1]=kf*yc; om[2]=kf*ang; om[3]=kf*score;
    out[KEEP_OFF + (size_t)b*KCAND + tid]=kf;
}

// ---------- finalize: enh_vis + ori_field (mask-predicated) ----------
__global__ void __launch_bounds__(256) finalize(const float* __restrict__ enh,
                         const float* __restrict__ oriup, float* __restrict__ out){
    int i=blockIdx.x*blockDim.x+threadIdx.x;
    if(i>=BNUM*NPIX) return;
    int b=i/NPIX, p=i%NPIX;
    float m=g_maskup[i];
    float emin=ord2f(g_emin[b]);
    float emax=ord2f(g_emax[b]);
    float e=enh[i]*m;
    out[ENH_OFF+i]=(e-emin)/(emax-emin+1e-8f)*255.0f;
    float of=0.0f;
    if(m!=0.0f){
        const float* o=oriup+(size_t)b*CORI*NPIX+p;
        int ai=0; float bv=o[0];
        for(int ch=1;ch<CORI;ch++){ float v=o[(size_t)ch*NPIX]; if(v>bv){bv=v;ai=ch;} }
        of=((float)ai*2.0f-90.0f)*0.017453292519943295f*m;
    }
    out[ORI_OFF+i]=of;
}

extern "C" void kernel_launch(void* const* d_in, const int* in_sizes, int n_in,
                              void* d_out, int out_size){
    const float* seg    =(const float*)d_in[0];
    const float* segup  =(const float*)d_in[1];
    const float* oriup  =(const float*)d_in[2];
    const float* enh    =(const float*)d_in[3];
    const float* mscore =(const float*)d_in[4];
    const float* mori   =(const float*)d_in[5];
    const float* mxo    =(const float*)d_in[6];
    const float* myo    =(const float*)d_in[7];
    float* out=(float*)d_out;

    dim3 hg(HU, BNUM);
    dim3 tg(16, 16, BNUM);
    dim3 tb(32, 8);

    opening_small<<<BNUM,1024>>>(seg);                               // + minmax init
    // opening40 = hmax(T(vmax(vmin(T(hmin(rint(segup)))))))  — all row-direction kernels
    hpool<true ,true ,false><<<hg,256>>>(segup, g_tA, nullptr, nullptr);  // hmin + rint
    transpose512<<<tg,tb>>>(g_tA, g_tB);
    hpool<true ,false,false><<<hg,256>>>(g_tB, g_tA, nullptr, nullptr);   // vmin (transposed)
    hpool<false,false,false><<<hg,256>>>(g_tA, g_tB, nullptr, nullptr);   // vmax (transposed)
    transpose512<<<tg,tb>>>(g_tB, g_tA);
    hpool<false,false,true ><<<hg,256>>>(g_tA, g_maskup, enh, out);       // hmax + mask + minmax

    detect_nms<<<BNUM,1024>>>(mscore, mori, mxo, myo, out);

    int nBig=(BNUM*NPIX+255)/256;
    finalize<<<nBig,256>>>(enh, oriup, out);
}